// round 5
// baseline (speedup 1.0000x reference)
#include <cuda_runtime.h>

#define HDIM 4
#define TSTEPS 7

__device__ __forceinline__ float htanh(float x) {
    float r;
    asm("tanh.approx.f32 %0, %1;" : "=f"(r) : "f"(x));
    return r;
}

__global__ __launch_bounds__(256, 3)
void rec_policy_kernel(const float* __restrict__ x,
                       const float* __restrict__ Wih_up, const float* __restrict__ Whh_up,
                       const float* __restrict__ bih_up, const float* __restrict__ bhh_up,
                       const float* __restrict__ W1,     const float* __restrict__ b1,
                       const float* __restrict__ W2,     const float* __restrict__ b2,
                       const float* __restrict__ Wih_dn, const float* __restrict__ Whh_dn,
                       const float* __restrict__ bih_dn, const float* __restrict__ bhh_dn,
                       const float* __restrict__ Wo,     const float* __restrict__ bo,
                       float* __restrict__ out, int B)
{
    // h_up history, transposed [t*4+k][tid]: stride-1 across lanes, conflict-free,
    // warp-private (no block sync needed).
    __shared__ float hup_s[TSTEPS * HDIM][256];
    // warp-local staging: 576 floats per warp for x (32 rows x 18), reused for out
    // (224 floats = 32 rows x 7) after x is consumed.
    __shared__ float stage[8 * 576];

    const int tid  = threadIdx.x;
    const int lane = tid & 31;
    const int wid  = tid >> 5;
    const int warpRowBase = blockIdx.x * 256 + wid * 32;
    const int row = warpRowBase + lane;

    float* ws = stage + wid * 576;
    const bool fullWarp = (warpRowBase + 32 <= B);

    // ---- coalesced x load: warp's 2304B region as 144 float4, round-robin ----
    if (fullWarp) {
        const float4* gsrc = reinterpret_cast<const float4*>(x + (size_t)warpRowBase * 18);
        #pragma unroll
        for (int r = 0; r < 5; r++) {
            int e = r * 32 + lane;
            if (e < 144) reinterpret_cast<float4*>(ws)[e] = gsrc[e];
        }
        __syncwarp();
    }
    if (row >= B) return;

    // ---- gather this row's 18 floats (LDS.64, 16-lane phases conflict-free) ----
    float xr[18];
    if (fullWarp) {
        const float2* xp = reinterpret_cast<const float2*>(ws + lane * 18);
        #pragma unroll
        for (int k = 0; k < 9; k++) {
            float2 v = xp[k];
            xr[2*k] = v.x; xr[2*k+1] = v.y;
        }
    } else {
        const float2* xp = reinterpret_cast<const float2*>(x + (size_t)row * 18);
        #pragma unroll
        for (int k = 0; k < 9; k++) {
            float2 v = xp[k];
            xr[2*k] = v.x; xr[2*k+1] = v.y;
        }
    }
    const float* obs = xr;       // x[:, 0:4]
    const float* jj  = xr + 4;   // x[:, 4:11]
    const float* jjd = xr + 11;  // x[:, 11:18]

    float h[HDIM];

    // ================= UP PHASE =================
    {
        float4 wiu01 = reinterpret_cast<const float4*>(Wih_up)[0];
        float4 wiu23 = reinterpret_cast<const float4*>(Wih_up)[1];
        float4 whu[HDIM];
        #pragma unroll
        for (int i = 0; i < HDIM; i++) whu[i] = reinterpret_cast<const float4*>(Whh_up)[i];
        float4 bi = reinterpret_cast<const float4*>(bih_up)[0];
        float4 bh = reinterpret_cast<const float4*>(bhh_up)[0];
        float bu[HDIM] = {bi.x + bh.x, bi.y + bh.y, bi.z + bh.z, bi.w + bh.w};
        float wi0[HDIM] = {wiu01.x, wiu01.z, wiu23.x, wiu23.z};
        float wi1[HDIM] = {wiu01.y, wiu01.w, wiu23.y, wiu23.w};

        #pragma unroll
        for (int i = 0; i < HDIM; i++) h[i] = 0.f;

        #pragma unroll
        for (int s = 0; s < TSTEPS; s++) {
            const int ti = TSTEPS - 1 - s;
            float pre[HDIM];
            #pragma unroll
            for (int i = 0; i < HDIM; i++) {
                float p = bu[i];
                p = fmaf(wi0[i], jj[ti],  p);
                p = fmaf(wi1[i], jjd[ti], p);
                p = fmaf(whu[i].x, h[0], p);
                p = fmaf(whu[i].y, h[1], p);
                p = fmaf(whu[i].z, h[2], p);
                p = fmaf(whu[i].w, h[3], p);
                pre[i] = p;
            }
            #pragma unroll
            for (int i = 0; i < HDIM; i++) {
                h[i] = htanh(pre[i]);
                hup_s[ti*HDIM + i][tid] = h[i];
            }
        }
    }

    // ================= MLP PHASE (stream once-used weights) =================
    {
        float z[8];
        #pragma unroll
        for (int k = 0; k < 4; k++) { z[k] = obs[k]; z[4+k] = h[k]; }

        float4 c1 = reinterpret_cast<const float4*>(b1)[0];
        float cb1[HDIM] = {c1.x, c1.y, c1.z, c1.w};
        float h0[HDIM];
        #pragma unroll
        for (int i = 0; i < HDIM; i++) {
            float4 a = reinterpret_cast<const float4*>(W1)[2*i];
            float4 b = reinterpret_cast<const float4*>(W1)[2*i+1];
            float p = cb1[i];
            p = fmaf(a.x, z[0], p); p = fmaf(a.y, z[1], p);
            p = fmaf(a.z, z[2], p); p = fmaf(a.w, z[3], p);
            p = fmaf(b.x, z[4], p); p = fmaf(b.y, z[5], p);
            p = fmaf(b.z, z[6], p); p = fmaf(b.w, z[7], p);
            h0[i] = htanh(p);
        }

        float4 c2 = reinterpret_cast<const float4*>(b2)[0];
        float cb2[HDIM] = {c2.x, c2.y, c2.z, c2.w};
        #pragma unroll
        for (int i = 0; i < HDIM; i++) {
            float4 a = reinterpret_cast<const float4*>(W2)[i];
            float p = cb2[i];
            p = fmaf(a.x, h0[0], p); p = fmaf(a.y, h0[1], p);
            p = fmaf(a.z, h0[2], p); p = fmaf(a.w, h0[3], p);
            h[i] = htanh(p);
        }
    }

    // ================= DOWN PHASE =================
    {
        float4 wid4[HDIM], whd[HDIM];
        #pragma unroll
        for (int i = 0; i < HDIM; i++) {
            wid4[i] = reinterpret_cast<const float4*>(Wih_dn)[i];
            whd[i]  = reinterpret_cast<const float4*>(Whh_dn)[i];
        }
        float4 bi = reinterpret_cast<const float4*>(bih_dn)[0];
        float4 bh = reinterpret_cast<const float4*>(bhh_dn)[0];
        float bd[HDIM] = {bi.x + bh.x, bi.y + bh.y, bi.z + bh.z, bi.w + bh.w};
        float4 wo4 = reinterpret_cast<const float4*>(Wo)[0];
        float wo_j = Wo[4];
        float bo0  = bo[0];

        #pragma unroll
        for (int t = 0; t < TSTEPS; t++) {
            float a = fmaf(wo_j, jj[t], bo0);
            a = fmaf(wo4.x, h[0], a);
            a = fmaf(wo4.y, h[1], a);
            a = fmaf(wo4.z, h[2], a);
            a = fmaf(wo4.w, h[3], a);
            if (fullWarp) ws[t*32 + lane] = a;            // transposed, stride-1
            else          out[(size_t)row * TSTEPS + t] = a;

            float hu0 = hup_s[t*HDIM + 0][tid];
            float hu1 = hup_s[t*HDIM + 1][tid];
            float hu2 = hup_s[t*HDIM + 2][tid];
            float hu3 = hup_s[t*HDIM + 3][tid];

            float hn[HDIM];
            #pragma unroll
            for (int i = 0; i < HDIM; i++) {
                float p = bd[i];
                p = fmaf(wid4[i].x, hu0, p);
                p = fmaf(wid4[i].y, hu1, p);
                p = fmaf(wid4[i].z, hu2, p);
                p = fmaf(wid4[i].w, hu3, p);
                p = fmaf(whd[i].x, h[0], p);
                p = fmaf(whd[i].y, h[1], p);
                p = fmaf(whd[i].z, h[2], p);
                p = fmaf(whd[i].w, h[3], p);
                hn[i] = htanh(p);
            }
            #pragma unroll
            for (int i = 0; i < HDIM; i++) h[i] = hn[i];
        }
    }

    // ---- coalesced out store: warp's 896B region as 56 float4 ----
    if (fullWarp) {
        __syncwarp();
        float4* gdst = reinterpret_cast<float4*>(out + (size_t)warpRowBase * TSTEPS);
        #pragma unroll
        for (int r = 0; r < 2; r++) {
            int e = r * 32 + lane;
            if (e < 56) {
                int f0 = 4*e;
                float v0 = ws[(f0    % 7)*32 + (f0    )/7];
                float v1 = ws[((f0+1) % 7)*32 + (f0+1)/7];
                float v2 = ws[((f0+2) % 7)*32 + (f0+2)/7];
                float v3 = ws[((f0+3) % 7)*32 + (f0+3)/7];
                gdst[e] = make_float4(v0, v1, v2, v3);
            }
        }
    }
}

extern "C" void kernel_launch(void* const* d_in, const int* in_sizes, int n_in,
                              void* d_out, int out_size)
{
    const float* x      = (const float*)d_in[0];
    const float* Wih_up = (const float*)d_in[1];
    const float* Whh_up = (const float*)d_in[2];
    const float* bih_up = (const float*)d_in[3];
    const float* bhh_up = (const float*)d_in[4];
    const float* W1     = (const float*)d_in[5];
    const float* b1     = (const float*)d_in[6];
    const float* W2     = (const float*)d_in[7];
    const float* b2     = (const float*)d_in[8];
    const float* Wih_dn = (const float*)d_in[9];
    const float* Whh_dn = (const float*)d_in[10];
    const float* bih_dn = (const float*)d_in[11];
    const float* bhh_dn = (const float*)d_in[12];
    const float* Wo     = (const float*)d_in[13];
    const float* bo     = (const float*)d_in[14];
    float* out = (float*)d_out;

    int B = in_sizes[0] / 18;
    int threads = 256;
    int blocks = (B + threads - 1) / threads;
    rec_policy_kernel<<<blocks, threads>>>(x, Wih_up, Whh_up, bih_up, bhh_up,
                                           W1, b1, W2, b2,
                                           Wih_dn, Whh_dn, bih_dn, bhh_dn,
                                           Wo, bo, out, B);
}

// round 6
// speedup vs baseline: 1.3472x; 1.3472x over previous
#include <cuda_runtime.h>

#define TSTEPS 7
typedef unsigned long long u64;

// ---- f32x2 packed helpers (sm_100+ PTX) ----
__device__ __forceinline__ u64 pack2(float lo, float hi) {
    u64 r; asm("mov.b64 %0, {%1, %2};" : "=l"(r) : "f"(lo), "f"(hi)); return r;
}
__device__ __forceinline__ u64 dup2(float v) {
    u64 r; asm("mov.b64 %0, {%1, %1};" : "=l"(r) : "f"(v)); return r;
}
__device__ __forceinline__ void unpack2(u64 p, float& lo, float& hi) {
    asm("mov.b64 {%0, %1}, %2;" : "=f"(lo), "=f"(hi) : "l"(p));
}
__device__ __forceinline__ u64 fma2(u64 a, u64 b, u64 c) {
    u64 d; asm("fma.rn.f32x2 %0, %1, %2, %3;" : "=l"(d) : "l"(a), "l"(b), "l"(c)); return d;
}
__device__ __forceinline__ float htanh(float x) {
    float r; asm("tanh.approx.f32 %0, %1;" : "=f"(r) : "f"(x)); return r;
}
__device__ __forceinline__ u64 tanh2(u64 p) {
    float lo, hi; unpack2(p, lo, hi);
    return pack2(htanh(lo), htanh(hi));
}

// scalar fallback for tail rows (cold path)
__device__ void scalar_row(int row,
                           const float* x,
                           const float* Wih_up, const float* Whh_up,
                           const float* bih_up, const float* bhh_up,
                           const float* W1, const float* b1,
                           const float* W2, const float* b2,
                           const float* Wih_dn, const float* Whh_dn,
                           const float* bih_dn, const float* bhh_dn,
                           const float* Wo, const float* bo,
                           float* out)
{
    float xr[18];
    for (int k = 0; k < 18; k++) xr[k] = x[(size_t)row * 18 + k];
    const float* obs = xr; const float* jj = xr + 4; const float* jjd = xr + 11;
    float h[4] = {0,0,0,0}, hup[TSTEPS][4];
    for (int s = 0; s < TSTEPS; s++) {
        int ti = TSTEPS - 1 - s;
        float pre[4];
        for (int i = 0; i < 4; i++) {
            float p = bih_up[i] + bhh_up[i];
            p = fmaf(Wih_up[i*2+0], jj[ti], p);
            p = fmaf(Wih_up[i*2+1], jjd[ti], p);
            for (int k = 0; k < 4; k++) p = fmaf(Whh_up[i*4+k], h[k], p);
            pre[i] = p;
        }
        for (int i = 0; i < 4; i++) { h[i] = htanh(pre[i]); hup[ti][i] = h[i]; }
    }
    float z[8]; for (int k = 0; k < 4; k++) { z[k] = obs[k]; z[4+k] = h[k]; }
    float h0[4];
    for (int i = 0; i < 4; i++) {
        float p = b1[i];
        for (int k = 0; k < 8; k++) p = fmaf(W1[i*8+k], z[k], p);
        h0[i] = htanh(p);
    }
    for (int i = 0; i < 4; i++) {
        float p = b2[i];
        for (int k = 0; k < 4; k++) p = fmaf(W2[i*4+k], h0[k], p);
        h[i] = htanh(p);
    }
    for (int t = 0; t < TSTEPS; t++) {
        float a = fmaf(Wo[4], jj[t], bo[0]);
        for (int k = 0; k < 4; k++) a = fmaf(Wo[k], h[k], a);
        out[(size_t)row * TSTEPS + t] = a;
        float hn[4];
        for (int i = 0; i < 4; i++) {
            float p = bih_dn[i] + bhh_dn[i];
            for (int k = 0; k < 4; k++) {
                p = fmaf(Wih_dn[i*4+k], hup[t][k], p);
                p = fmaf(Whh_dn[i*4+k], h[k], p);
            }
            hn[i] = htanh(p);
        }
        for (int i = 0; i < 4; i++) h[i] = hn[i];
    }
}

__global__ __launch_bounds__(128, 4)
void rec_policy_kernel(const float* __restrict__ x,
                       const float* __restrict__ Wih_up, const float* __restrict__ Whh_up,
                       const float* __restrict__ bih_up, const float* __restrict__ bhh_up,
                       const float* __restrict__ W1,     const float* __restrict__ b1,
                       const float* __restrict__ W2,     const float* __restrict__ b2,
                       const float* __restrict__ Wih_dn, const float* __restrict__ Whh_dn,
                       const float* __restrict__ bih_dn, const float* __restrict__ bhh_dn,
                       const float* __restrict__ Wo,     const float* __restrict__ bo,
                       float* __restrict__ out, int B)
{
    __shared__ float xstage[4 * 1152];     // 4 warps x 64 rows x 18 floats
    __shared__ u64   hup_s[TSTEPS * 4 * 128]; // [slot][tid], packed pairs

    const int tid  = threadIdx.x;
    const int lane = tid & 31;
    const int wid  = tid >> 5;
    const int warpBase = (blockIdx.x * 128 + wid * 32) * 2; // first of warp's 64 rows
    const int r0 = warpBase + lane * 2;                     // this thread's row pair

    const bool fast = (warpBase + 64 <= B);
    if (!fast) {
        // cold tail: scalar, guarded
        if (r0 < B)     scalar_row(r0,   x, Wih_up, Whh_up, bih_up, bhh_up, W1, b1,
                                   W2, b2, Wih_dn, Whh_dn, bih_dn, bhh_dn, Wo, bo, out);
        if (r0 + 1 < B) scalar_row(r0+1, x, Wih_up, Whh_up, bih_up, bhh_up, W1, b1,
                                   W2, b2, Wih_dn, Whh_dn, bih_dn, bhh_dn, Wo, bo, out);
        return;
    }

    // ---- coalesced x load: 64 rows = 288 float4, round-robin, then warp-local gather ----
    {
        const float4* g = reinterpret_cast<const float4*>(x + (size_t)warpBase * 18);
        float4* s = reinterpret_cast<float4*>(xstage + wid * 1152);
        #pragma unroll
        for (int r = 0; r < 9; r++) s[r * 32 + lane] = g[r * 32 + lane];
    }
    __syncwarp();

    u64 X[18];  // X[j] = (x[r0][j], x[r0+1][j])
    {
        float xb[36];
        const float4* sp = reinterpret_cast<const float4*>(xstage + wid * 1152 + lane * 36);
        #pragma unroll
        for (int k = 0; k < 9; k++) {
            float4 v = sp[k];
            xb[4*k] = v.x; xb[4*k+1] = v.y; xb[4*k+2] = v.z; xb[4*k+3] = v.w;
        }
        #pragma unroll
        for (int j = 0; j < 18; j++) X[j] = pack2(xb[j], xb[18 + j]);
    }

    u64 h[4];

    // ================= UP PHASE =================
    {
        float4 wiu01 = reinterpret_cast<const float4*>(Wih_up)[0];
        float4 wiu23 = reinterpret_cast<const float4*>(Wih_up)[1];
        float4 bi = reinterpret_cast<const float4*>(bih_up)[0];
        float4 bh = reinterpret_cast<const float4*>(bhh_up)[0];
        u64 wi0[4] = {dup2(wiu01.x), dup2(wiu01.z), dup2(wiu23.x), dup2(wiu23.z)};
        u64 wi1[4] = {dup2(wiu01.y), dup2(wiu01.w), dup2(wiu23.y), dup2(wiu23.w)};
        u64 bu[4]  = {dup2(bi.x+bh.x), dup2(bi.y+bh.y), dup2(bi.z+bh.z), dup2(bi.w+bh.w)};
        u64 whu[16];
        #pragma unroll
        for (int i = 0; i < 4; i++) {
            float4 w = reinterpret_cast<const float4*>(Whh_up)[i];
            whu[4*i+0] = dup2(w.x); whu[4*i+1] = dup2(w.y);
            whu[4*i+2] = dup2(w.z); whu[4*i+3] = dup2(w.w);
        }

        #pragma unroll
        for (int i = 0; i < 4; i++) h[i] = 0ull;  // (0.f, 0.f)

        #pragma unroll
        for (int s = 0; s < TSTEPS; s++) {
            const int ti = TSTEPS - 1 - s;
            u64 jjv = X[4 + ti], jdv = X[11 + ti];
            u64 pre[4];
            #pragma unroll
            for (int i = 0; i < 4; i++) {
                u64 p = fma2(wi0[i], jjv, bu[i]);
                p = fma2(wi1[i], jdv, p);
                p = fma2(whu[4*i+0], h[0], p);
                p = fma2(whu[4*i+1], h[1], p);
                p = fma2(whu[4*i+2], h[2], p);
                p = fma2(whu[4*i+3], h[3], p);
                pre[i] = p;
            }
            #pragma unroll
            for (int i = 0; i < 4; i++) {
                h[i] = tanh2(pre[i]);
                hup_s[(ti*4 + i) * 128 + tid] = h[i];
            }
        }
    }

    // ================= MLP PHASE (stream once-used weights) =================
    {
        u64 z[8];
        #pragma unroll
        for (int k = 0; k < 4; k++) { z[k] = X[k]; z[4+k] = h[k]; }

        float4 c1 = reinterpret_cast<const float4*>(b1)[0];
        float cb1[4] = {c1.x, c1.y, c1.z, c1.w};
        u64 h0[4];
        #pragma unroll
        for (int i = 0; i < 4; i++) {
            float4 a = reinterpret_cast<const float4*>(W1)[2*i];
            float4 b = reinterpret_cast<const float4*>(W1)[2*i+1];
            u64 p = dup2(cb1[i]);
            p = fma2(dup2(a.x), z[0], p); p = fma2(dup2(a.y), z[1], p);
            p = fma2(dup2(a.z), z[2], p); p = fma2(dup2(a.w), z[3], p);
            p = fma2(dup2(b.x), z[4], p); p = fma2(dup2(b.y), z[5], p);
            p = fma2(dup2(b.z), z[6], p); p = fma2(dup2(b.w), z[7], p);
            h0[i] = tanh2(p);
        }

        float4 c2 = reinterpret_cast<const float4*>(b2)[0];
        float cb2[4] = {c2.x, c2.y, c2.z, c2.w};
        #pragma unroll
        for (int i = 0; i < 4; i++) {
            float4 a = reinterpret_cast<const float4*>(W2)[i];
            u64 p = dup2(cb2[i]);
            p = fma2(dup2(a.x), h0[0], p); p = fma2(dup2(a.y), h0[1], p);
            p = fma2(dup2(a.z), h0[2], p); p = fma2(dup2(a.w), h0[3], p);
            h[i] = tanh2(p);
        }
    }

    // ================= DOWN PHASE =================
    u64 acts[TSTEPS];
    {
        u64 wid4[16], whd[16], bd[4];
        #pragma unroll
        for (int i = 0; i < 4; i++) {
            float4 a = reinterpret_cast<const float4*>(Wih_dn)[i];
            float4 b = reinterpret_cast<const float4*>(Whh_dn)[i];
            wid4[4*i+0] = dup2(a.x); wid4[4*i+1] = dup2(a.y);
            wid4[4*i+2] = dup2(a.z); wid4[4*i+3] = dup2(a.w);
            whd [4*i+0] = dup2(b.x); whd [4*i+1] = dup2(b.y);
            whd [4*i+2] = dup2(b.z); whd [4*i+3] = dup2(b.w);
        }
        {
            float4 bi = reinterpret_cast<const float4*>(bih_dn)[0];
            float4 bh = reinterpret_cast<const float4*>(bhh_dn)[0];
            bd[0] = dup2(bi.x+bh.x); bd[1] = dup2(bi.y+bh.y);
            bd[2] = dup2(bi.z+bh.z); bd[3] = dup2(bi.w+bh.w);
        }
        float4 wo_ = reinterpret_cast<const float4*>(Wo)[0];
        u64 wo0 = dup2(wo_.x), wo1 = dup2(wo_.y), wo2 = dup2(wo_.z), wo3 = dup2(wo_.w);
        u64 woj = dup2(Wo[4]);
        u64 bov = dup2(bo[0]);

        #pragma unroll
        for (int t = 0; t < TSTEPS; t++) {
            u64 a = fma2(woj, X[4 + t], bov);
            a = fma2(wo0, h[0], a);
            a = fma2(wo1, h[1], a);
            a = fma2(wo2, h[2], a);
            a = fma2(wo3, h[3], a);
            acts[t] = a;

            u64 hu0 = hup_s[(t*4 + 0) * 128 + tid];
            u64 hu1 = hup_s[(t*4 + 1) * 128 + tid];
            u64 hu2 = hup_s[(t*4 + 2) * 128 + tid];
            u64 hu3 = hup_s[(t*4 + 3) * 128 + tid];

            u64 hn[4];
            #pragma unroll
            for (int i = 0; i < 4; i++) {
                u64 p = bd[i];
                p = fma2(wid4[4*i+0], hu0, p);
                p = fma2(wid4[4*i+1], hu1, p);
                p = fma2(wid4[4*i+2], hu2, p);
                p = fma2(wid4[4*i+3], hu3, p);
                p = fma2(whd[4*i+0], h[0], p);
                p = fma2(whd[4*i+1], h[1], p);
                p = fma2(whd[4*i+2], h[2], p);
                p = fma2(whd[4*i+3], h[3], p);
                hn[i] = tanh2(p);
            }
            #pragma unroll
            for (int i = 0; i < 4; i++) h[i] = hn[i];
        }
    }

    // ---- output: rows (r0, r0+1) -> 14 contiguous floats at out + r0*7 (8B aligned) ----
    {
        float a0[TSTEPS], a1[TSTEPS];
        #pragma unroll
        for (int t = 0; t < TSTEPS; t++) unpack2(acts[t], a0[t], a1[t]);
        float2* o = reinterpret_cast<float2*>(out + (size_t)r0 * TSTEPS);
        o[0] = make_float2(a0[0], a0[1]);
        o[1] = make_float2(a0[2], a0[3]);
        o[2] = make_float2(a0[4], a0[5]);
        o[3] = make_float2(a0[6], a1[0]);
        o[4] = make_float2(a1[1], a1[2]);
        o[5] = make_float2(a1[3], a1[4]);
        o[6] = make_float2(a1[5], a1[6]);
    }
}

extern "C" void kernel_launch(void* const* d_in, const int* in_sizes, int n_in,
                              void* d_out, int out_size)
{
    const float* x      = (const float*)d_in[0];
    const float* Wih_up = (const float*)d_in[1];
    const float* Whh_up = (const float*)d_in[2];
    const float* bih_up = (const float*)d_in[3];
    const float* bhh_up = (const float*)d_in[4];
    const float* W1     = (const float*)d_in[5];
    const float* b1     = (const float*)d_in[6];
    const float* W2     = (const float*)d_in[7];
    const float* b2     = (const float*)d_in[8];
    const float* Wih_dn = (const float*)d_in[9];
    const float* Whh_dn = (const float*)d_in[10];
    const float* bih_dn = (const float*)d_in[11];
    const float* bhh_dn = (const float*)d_in[12];
    const float* Wo     = (const float*)d_in[13];
    const float* bo     = (const float*)d_in[14];
    float* out = (float*)d_out;

    int B = in_sizes[0] / 18;
    int rowsPerBlock = 256;            // 128 threads x 2 rows
    int blocks = (B + rowsPerBlock - 1) / rowsPerBlock;
    rec_policy_kernel<<<blocks, 128>>>(x, Wih_up, Whh_up, bih_up, bhh_up,
                                       W1, b1, W2, b2,
                                       Wih_dn, Whh_dn, bih_dn, bhh_dn,
                                       Wo, bo, out, B);
}

// round 7
// speedup vs baseline: 1.3601x; 1.0096x over previous
#include <cuda_runtime.h>

#define TSTEPS 7
typedef unsigned long long u64;

// ---- f32x2 packed helpers (sm_100+ PTX) ----
__device__ __forceinline__ u64 pack2(float lo, float hi) {
    u64 r; asm("mov.b64 %0, {%1, %2};" : "=l"(r) : "f"(lo), "f"(hi)); return r;
}
__device__ __forceinline__ u64 dup2(float v) {
    u64 r; asm("mov.b64 %0, {%1, %1};" : "=l"(r) : "f"(v)); return r;
}
__device__ __forceinline__ void unpack2(u64 p, float& lo, float& hi) {
    asm("mov.b64 {%0, %1}, %2;" : "=f"(lo), "=f"(hi) : "l"(p));
}
__device__ __forceinline__ u64 fma2(u64 a, u64 b, u64 c) {
    u64 d; asm("fma.rn.f32x2 %0, %1, %2, %3;" : "=l"(d) : "l"(a), "l"(b), "l"(c)); return d;
}
__device__ __forceinline__ float htanh(float x) {
    float r; asm("tanh.approx.f32 %0, %1;" : "=f"(r) : "f"(x)); return r;
}
__device__ __forceinline__ u64 tanh2(u64 p) {
    float lo, hi; unpack2(p, lo, hi);
    return pack2(htanh(lo), htanh(hi));
}

// scalar fallback for tail rows (cold path)
__device__ void scalar_row(int row,
                           const float* x,
                           const float* Wih_up, const float* Whh_up,
                           const float* bih_up, const float* bhh_up,
                           const float* W1, const float* b1,
                           const float* W2, const float* b2,
                           const float* Wih_dn, const float* Whh_dn,
                           const float* bih_dn, const float* bhh_dn,
                           const float* Wo, const float* bo,
                           float* out)
{
    float xr[18];
    for (int k = 0; k < 18; k++) xr[k] = x[(size_t)row * 18 + k];
    const float* obs = xr; const float* jj = xr + 4; const float* jjd = xr + 11;
    float h[4] = {0,0,0,0}, hup[TSTEPS][4];
    for (int s = 0; s < TSTEPS; s++) {
        int ti = TSTEPS - 1 - s;
        float pre[4];
        for (int i = 0; i < 4; i++) {
            float p = bih_up[i] + bhh_up[i];
            p = fmaf(Wih_up[i*2+0], jj[ti], p);
            p = fmaf(Wih_up[i*2+1], jjd[ti], p);
            for (int k = 0; k < 4; k++) p = fmaf(Whh_up[i*4+k], h[k], p);
            pre[i] = p;
        }
        for (int i = 0; i < 4; i++) { h[i] = htanh(pre[i]); hup[ti][i] = h[i]; }
    }
    float z[8]; for (int k = 0; k < 4; k++) { z[k] = obs[k]; z[4+k] = h[k]; }
    float h0[4];
    for (int i = 0; i < 4; i++) {
        float p = b1[i];
        for (int k = 0; k < 8; k++) p = fmaf(W1[i*8+k], z[k], p);
        h0[i] = htanh(p);
    }
    for (int i = 0; i < 4; i++) {
        float p = b2[i];
        for (int k = 0; k < 4; k++) p = fmaf(W2[i*4+k], h0[k], p);
        h[i] = htanh(p);
    }
    for (int t = 0; t < TSTEPS; t++) {
        float a = fmaf(Wo[4], jj[t], bo[0]);
        for (int k = 0; k < 4; k++) a = fmaf(Wo[k], h[k], a);
        out[(size_t)row * TSTEPS + t] = a;
        float hn[4];
        for (int i = 0; i < 4; i++) {
            float p = bih_dn[i] + bhh_dn[i];
            for (int k = 0; k < 4; k++) {
                p = fmaf(Wih_dn[i*4+k], hup[t][k], p);
                p = fmaf(Whh_dn[i*4+k], h[k], p);
            }
            hn[i] = htanh(p);
        }
        for (int i = 0; i < 4; i++) h[i] = hn[i];
    }
}

__global__ __launch_bounds__(128, 4)
void rec_policy_kernel(const float* __restrict__ x,
                       const float* __restrict__ Wih_up, const float* __restrict__ Whh_up,
                       const float* __restrict__ bih_up, const float* __restrict__ bhh_up,
                       const float* __restrict__ W1,     const float* __restrict__ b1,
                       const float* __restrict__ W2,     const float* __restrict__ b2,
                       const float* __restrict__ Wih_dn, const float* __restrict__ Whh_dn,
                       const float* __restrict__ bih_dn, const float* __restrict__ bhh_dn,
                       const float* __restrict__ Wo,     const float* __restrict__ bo,
                       float* __restrict__ out, int B)
{
    __shared__ float xstage[4 * 1152];        // 4 warps x 64 rows x 18 floats
    __shared__ u64   hup_s[TSTEPS * 4 * 128]; // [slot][tid], packed pairs; slots reused for acts

    const int tid  = threadIdx.x;
    const int lane = tid & 31;
    const int wid  = tid >> 5;
    const int warpBase = (blockIdx.x * 128 + wid * 32) * 2; // first of warp's 64 rows
    const int r0 = warpBase + lane * 2;                     // this thread's row pair

    const bool fast = (warpBase + 64 <= B);
    if (!fast) {
        if (r0 < B)     scalar_row(r0,   x, Wih_up, Whh_up, bih_up, bhh_up, W1, b1,
                                   W2, b2, Wih_dn, Whh_dn, bih_dn, bhh_dn, Wo, bo, out);
        if (r0 + 1 < B) scalar_row(r0+1, x, Wih_up, Whh_up, bih_up, bhh_up, W1, b1,
                                   W2, b2, Wih_dn, Whh_dn, bih_dn, bhh_dn, Wo, bo, out);
        return;
    }

    // ---- coalesced x load: 64 rows = 288 float4, round-robin, then warp-local gather ----
    {
        const float4* g = reinterpret_cast<const float4*>(x + (size_t)warpBase * 18);
        float4* s = reinterpret_cast<float4*>(xstage + wid * 1152);
        #pragma unroll
        for (int r = 0; r < 9; r++) s[r * 32 + lane] = g[r * 32 + lane];
    }
    __syncwarp();

    u64 X[18];  // X[j] = (x[r0][j], x[r0+1][j])
    {
        float xb[36];
        const float4* sp = reinterpret_cast<const float4*>(xstage + wid * 1152 + lane * 36);
        #pragma unroll
        for (int k = 0; k < 9; k++) {
            float4 v = sp[k];
            xb[4*k] = v.x; xb[4*k+1] = v.y; xb[4*k+2] = v.z; xb[4*k+3] = v.w;
        }
        #pragma unroll
        for (int j = 0; j < 18; j++) X[j] = pack2(xb[j], xb[18 + j]);
    }

    u64 h[4];

    // ================= UP PHASE =================
    {
        float4 wiu01 = reinterpret_cast<const float4*>(Wih_up)[0];
        float4 wiu23 = reinterpret_cast<const float4*>(Wih_up)[1];
        float4 bi = reinterpret_cast<const float4*>(bih_up)[0];
        float4 bh = reinterpret_cast<const float4*>(bhh_up)[0];
        u64 wi0[4] = {dup2(wiu01.x), dup2(wiu01.z), dup2(wiu23.x), dup2(wiu23.z)};
        u64 wi1[4] = {dup2(wiu01.y), dup2(wiu01.w), dup2(wiu23.y), dup2(wiu23.w)};
        u64 bu[4]  = {dup2(bi.x+bh.x), dup2(bi.y+bh.y), dup2(bi.z+bh.z), dup2(bi.w+bh.w)};
        u64 whu[16];
        #pragma unroll
        for (int i = 0; i < 4; i++) {
            float4 w = reinterpret_cast<const float4*>(Whh_up)[i];
            whu[4*i+0] = dup2(w.x); whu[4*i+1] = dup2(w.y);
            whu[4*i+2] = dup2(w.z); whu[4*i+3] = dup2(w.w);
        }

        #pragma unroll
        for (int i = 0; i < 4; i++) h[i] = 0ull;

        #pragma unroll
        for (int s = 0; s < TSTEPS; s++) {
            const int ti = TSTEPS - 1 - s;
            u64 jjv = X[4 + ti], jdv = X[11 + ti];
            u64 pre[4];
            #pragma unroll
            for (int i = 0; i < 4; i++) {
                u64 p = fma2(wi0[i], jjv, bu[i]);
                p = fma2(wi1[i], jdv, p);
                p = fma2(whu[4*i+0], h[0], p);
                p = fma2(whu[4*i+1], h[1], p);
                p = fma2(whu[4*i+2], h[2], p);
                p = fma2(whu[4*i+3], h[3], p);
                pre[i] = p;
            }
            #pragma unroll
            for (int i = 0; i < 4; i++) {
                h[i] = tanh2(pre[i]);
                hup_s[(ti*4 + i) * 128 + tid] = h[i];
            }
        }
    }

    // ================= MLP PHASE (stream once-used weights) =================
    {
        u64 z[8];
        #pragma unroll
        for (int k = 0; k < 4; k++) { z[k] = X[k]; z[4+k] = h[k]; }

        float4 c1 = reinterpret_cast<const float4*>(b1)[0];
        float cb1[4] = {c1.x, c1.y, c1.z, c1.w};
        u64 h0[4];
        #pragma unroll
        for (int i = 0; i < 4; i++) {
            float4 a = reinterpret_cast<const float4*>(W1)[2*i];
            float4 b = reinterpret_cast<const float4*>(W1)[2*i+1];
            u64 p = dup2(cb1[i]);
            p = fma2(dup2(a.x), z[0], p); p = fma2(dup2(a.y), z[1], p);
            p = fma2(dup2(a.z), z[2], p); p = fma2(dup2(a.w), z[3], p);
            p = fma2(dup2(b.x), z[4], p); p = fma2(dup2(b.y), z[5], p);
            p = fma2(dup2(b.z), z[6], p); p = fma2(dup2(b.w), z[7], p);
            h0[i] = tanh2(p);
        }

        float4 c2 = reinterpret_cast<const float4*>(b2)[0];
        float cb2[4] = {c2.x, c2.y, c2.z, c2.w};
        #pragma unroll
        for (int i = 0; i < 4; i++) {
            float4 a = reinterpret_cast<const float4*>(W2)[i];
            u64 p = dup2(cb2[i]);
            p = fma2(dup2(a.x), h0[0], p); p = fma2(dup2(a.y), h0[1], p);
            p = fma2(dup2(a.z), h0[2], p); p = fma2(dup2(a.w), h0[3], p);
            h[i] = tanh2(p);
        }
    }

    // ================= DOWN PHASE =================
    // acts[t] is written into the just-consumed hup slot (t*4+0) to keep the
    // loop's live register set under the 128-reg cap (no spills).
    {
        u64 wid4[16], whd[16], bd[4];
        #pragma unroll
        for (int i = 0; i < 4; i++) {
            float4 a = reinterpret_cast<const float4*>(Wih_dn)[i];
            float4 b = reinterpret_cast<const float4*>(Whh_dn)[i];
            wid4[4*i+0] = dup2(a.x); wid4[4*i+1] = dup2(a.y);
            wid4[4*i+2] = dup2(a.z); wid4[4*i+3] = dup2(a.w);
            whd [4*i+0] = dup2(b.x); whd [4*i+1] = dup2(b.y);
            whd [4*i+2] = dup2(b.z); whd [4*i+3] = dup2(b.w);
        }
        {
            float4 bi = reinterpret_cast<const float4*>(bih_dn)[0];
            float4 bh = reinterpret_cast<const float4*>(bhh_dn)[0];
            bd[0] = dup2(bi.x+bh.x); bd[1] = dup2(bi.y+bh.y);
            bd[2] = dup2(bi.z+bh.z); bd[3] = dup2(bi.w+bh.w);
        }
        float4 wo_ = reinterpret_cast<const float4*>(Wo)[0];
        u64 wo0 = dup2(wo_.x), wo1 = dup2(wo_.y), wo2 = dup2(wo_.z), wo3 = dup2(wo_.w);
        u64 woj = dup2(Wo[4]);
        u64 bov = dup2(bo[0]);

        #pragma unroll
        for (int t = 0; t < TSTEPS; t++) {
            u64 hu0 = hup_s[(t*4 + 0) * 128 + tid];
            u64 hu1 = hup_s[(t*4 + 1) * 128 + tid];
            u64 hu2 = hup_s[(t*4 + 2) * 128 + tid];
            u64 hu3 = hup_s[(t*4 + 3) * 128 + tid];

            u64 a = fma2(woj, X[4 + t], bov);
            a = fma2(wo0, h[0], a);
            a = fma2(wo1, h[1], a);
            a = fma2(wo2, h[2], a);
            a = fma2(wo3, h[3], a);
            hup_s[(t*4 + 0) * 128 + tid] = a;   // park acts[t] in dead slot

            u64 hn[4];
            #pragma unroll
            for (int i = 0; i < 4; i++) {
                u64 p = bd[i];
                p = fma2(wid4[4*i+0], hu0, p);
                p = fma2(wid4[4*i+1], hu1, p);
                p = fma2(wid4[4*i+2], hu2, p);
                p = fma2(wid4[4*i+3], hu3, p);
                p = fma2(whd[4*i+0], h[0], p);
                p = fma2(whd[4*i+1], h[1], p);
                p = fma2(whd[4*i+2], h[2], p);
                p = fma2(whd[4*i+3], h[3], p);
                hn[i] = tanh2(p);
            }
            #pragma unroll
            for (int i = 0; i < 4; i++) h[i] = hn[i];
        }
    }

    // ---- output flush: read parked acts, rows (r0, r0+1) -> 14 contiguous floats ----
    {
        float a0[TSTEPS], a1[TSTEPS];
        #pragma unroll
        for (int t = 0; t < TSTEPS; t++)
            unpack2(hup_s[(t*4 + 0) * 128 + tid], a0[t], a1[t]);
        float2* o = reinterpret_cast<float2*>(out + (size_t)r0 * TSTEPS);
        o[0] = make_float2(a0[0], a0[1]);
        o[1] = make_float2(a0[2], a0[3]);
        o[2] = make_float2(a0[4], a0[5]);
        o[3] = make_float2(a0[6], a1[0]);
        o[4] = make_float2(a1[1], a1[2]);
        o[5] = make_float2(a1[3], a1[4]);
        o[6] = make_float2(a1[5], a1[6]);
    }
}

extern "C" void kernel_launch(void* const* d_in, const int* in_sizes, int n_in,
                              void* d_out, int out_size)
{
    const float* x      = (const float*)d_in[0];
    const float* Wih_up = (const float*)d_in[1];
    const float* Whh_up = (const float*)d_in[2];
    const float* bih_up = (const float*)d_in[3];
    const float* bhh_up = (const float*)d_in[4];
    const float* W1     = (const float*)d_in[5];
    const float* b1     = (const float*)d_in[6];
    const float* W2     = (const float*)d_in[7];
    const float* b2     = (const float*)d_in[8];
    const float* Wih_dn = (const float*)d_in[9];
    const float* Whh_dn = (const float*)d_in[10];
    const float* bih_dn = (const float*)d_in[11];
    const float* bhh_dn = (const float*)d_in[12];
    const float* Wo     = (const float*)d_in[13];
    const float* bo     = (const float*)d_in[14];
    float* out = (float*)d_out;

    int B = in_sizes[0] / 18;
    int rowsPerBlock = 256;            // 128 threads x 2 rows
    int blocks = (B + rowsPerBlock - 1) / rowsPerBlock;
    rec_policy_kernel<<<blocks, 128>>>(x, Wih_up, Whh_up, bih_up, bhh_up,
                                       W1, b1, W2, b2,
                                       Wih_dn, Whh_dn, bih_dn, bhh_dn,
                                       Wo, bo, out, B);
}